// round 16
// baseline (speedup 1.0000x reference)
#include <cuda_runtime.h>
#include <math.h>
#include <stdint.h>

#define BB 8
#define NN 8192
#define NP 2048
#define NS 32
#define DINC 61
#define DD 64
#define FPSC 4   // FPS CTAs per batch

typedef unsigned long long ull;
__device__ __forceinline__ ull pack2(float lo, float hi) {
    ull r; asm("mov.b64 %0, {%1,%2};" : "=l"(r) : "f"(lo), "f"(hi)); return r;
}
__device__ __forceinline__ float2 unpack2(ull v) {
    float2 r; asm("mov.b64 {%0,%1}, %2;" : "=f"(r.x), "=f"(r.y) : "l"(v)); return r;
}
__device__ __forceinline__ ull ffma2(ull a, ull b, ull c) {
    ull d; asm("fma.rn.f32x2 %0, %1, %2, %3;" : "=l"(d) : "l"(a), "l"(b), "l"(c)); return d;
}
__device__ __forceinline__ ull fadd2(ull a, ull b) {
    ull d; asm("add.rn.f32x2 %0, %1, %2;" : "=l"(d) : "l"(a), "l"(b)); return d;
}
__device__ __forceinline__ ull fmul2(ull a, ull b) {
    ull d; asm("mul.rn.f32x2 %0, %1, %2;" : "=l"(d) : "l"(a), "l"(b)); return d;
}
__device__ __forceinline__ void stg_release(ull* p, ull v) {
    asm volatile("st.global.release.gpu.u64 [%0], %1;" :: "l"(p), "l"(v) : "memory");
}
__device__ __forceinline__ ull ldg_acquire(const ull* p) {
    ull v; asm volatile("ld.global.acquire.gpu.u64 %0, [%1];" : "=l"(v) : "l"(p) : "memory");
    return v;
}

__device__ float g_newxyz[BB * NP * 3];
__device__ int   g_gi[BB * NP * NS];
__device__ float g_feat2[BB * NP * DD];
__device__ float g_qp[BB * NP * DD];
__device__ float g_v[BB * NP * DD];
__device__ float g_o[BB * NP * DD];
__device__ float g_M1[DD * DD];
__device__ float g_M2[DD * DD];
__device__ ull   g_sync[BB * NP * FPSC];   // write-once per launch

// ---------------- zero the FPS mailbox (replay-deterministic) ----------------
__global__ void __launch_bounds__(256) zerosync_kernel() {
    g_sync[blockIdx.x * 256 + threadIdx.x] = 0ull;
}

// ---------------- M = 0.125 * Wq @ Wk^T ----------------
__global__ void __launch_bounds__(256) mprep_kernel(
    const float* __restrict__ q1, const float* __restrict__ k1,
    const float* __restrict__ q2, const float* __restrict__ k2) {
    __shared__ float sq[4096], sk[4096];
    const float* q = blockIdx.x ? q2 : q1;
    const float* k = blockIdx.x ? k2 : k1;
    float* M = blockIdx.x ? g_M2 : g_M1;
    const int tid = threadIdx.x;
    for (int i = tid; i < 4096; i += 256) { sq[i] = q[i]; sk[i] = k[i]; }
    __syncthreads();
    for (int o = 0; o < 16; ++o) {
        const int idx = tid + o * 256;
        const int a = idx >> 6, c = idx & 63;
        float s = 0.f;
#pragma unroll 8
        for (int d = 0; d < 64; ++d) s += sq[a * 64 + d] * sk[c * 64 + d];
        M[idx] = 0.125f * s;
    }
}

// ---------------- FPS: 4 CTAs/batch, PROVEN mailbox protocol, warp0-only polling ----------------
// R15 proved correctness (write-once g_sync + release/acquire). This round fixes
// the polling storm: only warp0 reduces/stores/polls; lanes 0-3 each poll ONE
// slot; cur broadcast via smem. 256x less L2 poll traffic.
__global__ void __launch_bounds__(1024) fps_kernel(const float* __restrict__ xyz,
                                                   float* __restrict__ out1) {
    extern __shared__ float sm[];
    float* sx  = sm;
    float* sy  = sm + NN;
    float* sz  = sm + 2 * NN;
    ull*  wkey = (ull*)(sm + 3 * NN);        // 2 x 32 parity slots
    int*  scur = (int*)(wkey + 64);          // 1 int

    const int b    = blockIdx.x >> 2;
    const int rank = blockIdx.x & 3;
    const int tid  = threadIdx.x;
    const int lane = tid & 31, wid = tid >> 5;
    const float* xb = xyz + (size_t)b * 3 * NN;

    for (int i = tid; i < NN; i += 1024) {
        sx[i] = xb[i]; sy[i] = xb[NN + i]; sz[i] = xb[2 * NN + i];
    }
    __syncthreads();

    // slice: global points i0 = rank*2048 + tid, i1 = i0 + 1024
    const int i0 = rank * 2048 + tid, i1 = i0 + 1024;
    const ull x2 = pack2(sx[i0], sx[i1]);
    const ull y2 = pack2(sy[i0], sy[i1]);
    const ull z2 = pack2(sz[i0], sz[i1]);
    float pd0 = 1e10f, pd1 = 1e10f;

    int cur = 0;
    for (int it = 0; it < NP; ++it) {
        const int p = it & 1;
        const float c0 = sx[cur], c1 = sy[cur], c2 = sz[cur];
        if (rank == 0 && tid == 0) {
            g_newxyz[((size_t)b * NP + it) * 3 + 0] = c0;
            g_newxyz[((size_t)b * NP + it) * 3 + 1] = c1;
            g_newxyz[((size_t)b * NP + it) * 3 + 2] = c2;
            out1[(size_t)b * 3 * NP + it]          = c0;
            out1[(size_t)b * 3 * NP + NP + it]     = c1;
            out1[(size_t)b * 3 * NP + 2 * NP + it] = c2;
        }
        // distance math: BIT-IDENTICAL to XLA elementwise lowering (no FMA;
        // x + (-c) == x - c in IEEE; f32x2 ops are componentwise RN)
        const ull n0 = pack2(-c0, -c0), n1 = pack2(-c1, -c1), n2 = pack2(-c2, -c2);
        const ull dx = fadd2(x2, n0);
        const ull dy = fadd2(y2, n1);
        const ull dz = fadd2(z2, n2);
        const ull dd = fadd2(fadd2(fmul2(dx, dx), fmul2(dy, dy)), fmul2(dz, dz));
        const float2 dv = unpack2(dd);
        pd0 = fminf(pd0, dv.x);
        pd1 = fminf(pd1, dv.y);
        float tmax = pd0; int kb = i0;
        if (pd1 > tmax) { tmax = pd1; kb = i1; }   // strict >: first-occurrence

        // stage 1: warp reduce (positive floats: uint bit order == float order)
        const unsigned tb = __float_as_uint(tmax);
        const unsigned wm = __reduce_max_sync(0xffffffffu, tb);
        const unsigned inv = __reduce_max_sync(0xffffffffu,
                                               (tb == wm) ? ~(unsigned)kb : 0u);
        ull* buf = wkey + p * 32;
        if (lane == 0) buf[wid] = ((ull)wm << 32) | (ull)inv;
        __syncthreads();                       // BAR1: wkey ready

        if (wid == 0) {
            // stage 2: warp0 reduces the 32 warp keys
            const ull k = buf[lane];
            const unsigned hi = (unsigned)(k >> 32), lo = (unsigned)k;
            const unsigned m2 = __reduce_max_sync(0xffffffffu, hi);
            const unsigned inv2 = __reduce_max_sync(0xffffffffu, (hi == m2) ? lo : 0u);
            const ull ctakey = ((ull)m2 << 32) | (ull)inv2;

            ull* slot = g_sync + ((size_t)b * NP + it) * FPSC;
            if (lane == 0) stg_release(slot + rank, ctakey);

            // lanes 0-3: each polls one slot (write-once => no reuse hazards)
            ull kk = 0;
            if (lane < 4) {
                do { kk = ldg_acquire(slot + lane); } while (kk == 0);
            }
            if (lane < 4) {
                const unsigned khi = (unsigned)(kk >> 32), klo = (unsigned)kk;
                const unsigned gm = __reduce_max_sync(0x0000000fu, khi);
                const unsigned gi = __reduce_max_sync(0x0000000fu,
                                                      (khi == gm) ? klo : 0u);
                if (lane == 0) scur[0] = (int)(~gi);
            }
        }
        __syncthreads();                       // BAR2: scur ready
        cur = scur[0];
    }
}

// ---------------- ball query (R9 proven) ----------------
__global__ void __launch_bounds__(256) ballquery_kernel(const float* __restrict__ xyz) {
    extern __shared__ float sm[];
    float* sx = sm;
    float* sy = sm + NN;
    float* sz = sm + 2 * NN;

    const int b   = blockIdx.y;
    const int tid = threadIdx.x;
    const float* xb = xyz + (size_t)b * 3 * NN;
    for (int i = tid; i < NN; i += 256) {
        sx[i] = xb[i]; sy[i] = xb[NN + i]; sz[i] = xb[2 * NN + i];
    }
    __syncthreads();

    const int wid = tid >> 5, lane = tid & 31;
    const int s = blockIdx.x * 8 + wid;
    const float r2 = (float)(0.2 * 0.2);

    const float c0 = g_newxyz[((size_t)b * NP + s) * 3 + 0];
    const float c1 = g_newxyz[((size_t)b * NP + s) * 3 + 1];
    const float c2 = g_newxyz[((size_t)b * NP + s) * 3 + 2];
    const float sqc = __fadd_rn(__fadd_rn(__fmul_rn(c0, c0), __fmul_rn(c1, c1)),
                                __fmul_rn(c2, c2));
    const size_t gbase = ((size_t)b * NP + s) * NS;

    int count = 0;
    int firstIdx = -1;
    for (int base = 0; base < NN && count < NS; base += 32) {
        const int i = base + lane;
        const float x = sx[i], y = sy[i], z = sz[i];
        const float sqx = __fadd_rn(__fadd_rn(__fmul_rn(x, x), __fmul_rn(y, y)),
                                    __fmul_rn(z, z));
        const float cx = fmaf(c2, z, fmaf(c1, y, __fmul_rn(c0, x)));
        const float sqr = __fsub_rn(__fadd_rn(sqc, sqx), __fmul_rn(2.0f, cx));
        const bool hit = !(sqr > r2);
        const unsigned mask = __ballot_sync(0xffffffffu, hit);
        if (firstIdx < 0 && mask) firstIdx = base + __ffs(mask) - 1;
        if (hit) {
            int slot = count + __popc(mask & ((1u << lane) - 1u));
            if (slot < NS) g_gi[gbase + slot] = i;
        }
        count += __popc(mask);
    }
    int cnt = count < NS ? count : NS;
    for (int j = cnt + lane; j < NS; j += 32) g_gi[gbase + j] = firstIdx;
}

// ---------------- attn1 (R9 proven; 64-reg safe) ----------------
#define A1_SMEM_BYTES 43008

__global__ void __launch_bounds__(256, 4) attn1_kernel(
    const float* __restrict__ xyz, const float* __restrict__ points,
    const float* __restrict__ wv, const float* __restrict__ wo,
    const float* __restrict__ wp, const float* __restrict__ bp) {
    extern __shared__ float sm[];
    float* ft  = sm;
    float* ftT = sm + 2176;
    float* tm  = sm + 4480;
    float* vm  = sm + 6656;
    float* sc  = sm + 8832;
    float* px  = sm + 9984;
    float* py  = sm + 10016;
    float* pz  = sm + 10048;
    float* red = sm + 10080;
    int* sidx  = (int*)(sm + 10592);
    float* om  = ftT;

    const int g   = blockIdx.x;
    const int b   = g >> 11;
    const int tid = threadIdx.x;
    const int lane = tid & 31, wid = tid >> 5;

    if (tid < 32) {
        const int id = g_gi[(size_t)g * NS + tid];
        sidx[tid] = id;
        const float c0 = g_newxyz[(size_t)g * 3 + 0];
        const float c1 = g_newxyz[(size_t)g * 3 + 1];
        const float c2 = g_newxyz[(size_t)g * 3 + 2];
        const float X = xyz[(size_t)b * 3 * NN + id];
        const float Y = xyz[(size_t)b * 3 * NN + NN + id];
        const float Z = xyz[(size_t)b * 3 * NN + 2 * NN + id];
        px[tid] = X; py[tid] = Y; pz[tid] = Z;
        ft[tid * 68 + 0] = X - c0;
        ft[tid * 68 + 1] = Y - c1;
        ft[tid * 68 + 2] = Z - c2;
    }
    __syncthreads();
    for (int i = tid; i < NS * DINC; i += 256) {
        const int c = i >> 5, j = i & 31;
        ft[j * 68 + 3 + c] = points[(size_t)b * DINC * NN + (size_t)c * NN + sidx[j]];
    }
    __syncthreads();

    const int thp = tid & 31;
    const int dp  = thp * 2;
    const int tgp = tid >> 5;
    {
        ull aM[4] = {0, 0, 0, 0}, aV[4] = {0, 0, 0, 0};
        const float* mp = g_M1 + dp;
        const float* vp = wv + dp;
#pragma unroll 4
        for (int e = 0; e < 64; ++e) {
            const ull m2 = *(const ull*)(mp + e * 64);
            const ull v2 = *(const ull*)(vp + e * 64);
#pragma unroll
            for (int r = 0; r < 4; ++r) {
                const float f = ft[(tgp + 8 * r) * 68 + e];
                const ull f2 = pack2(f, f);
                aM[r] = ffma2(f2, m2, aM[r]);
                aV[r] = ffma2(f2, v2, aV[r]);
            }
        }
        const ull wx = *(const ull*)(wp + dp);
        const ull wy = *(const ull*)(wp + 64 + dp);
        const ull wz = *(const ull*)(wp + 128 + dp);
        const ull wb = *(const ull*)(bp + dp);
#pragma unroll
        for (int r = 0; r < 4; ++r) {
            const int row = tgp + 8 * r;
            aV[r] = ffma2(pack2(px[row], px[row]), wx, aV[r]);
            aV[r] = ffma2(pack2(py[row], py[row]), wy, aV[r]);
            aV[r] = ffma2(pack2(pz[row], pz[row]), wz, aV[r]);
            aV[r] = fadd2(aV[r], wb);
            *(ull*)&tm[row * 68 + dp] = aM[r];
            *(ull*)&vm[row * 68 + dp] = aV[r];
        }
    }
#pragma unroll
    for (int r = 0; r < 8; ++r) {
        const int idx = tid + r * 256;
        const int e = idx >> 5, j = idx & 31;
        ftT[e * 36 + j] = ft[j * 68 + e];
    }
    __syncthreads();

    const int ths = tid & 15;
    const int ts  = tid >> 4;
    {
        const int j0 = ths * 2;
        ull sA = 0, sB = 0;
        const float* trA = tm + ts * 68;
        const float* trB = tm + (ts + 16) * 68;
#pragma unroll 8
        for (int e = 0; e < 64; ++e) {
            const ull fj = *(const ull*)&ftT[e * 36 + j0];
            sA = ffma2(pack2(trA[e], trA[e]), fj, sA);
            sB = ffma2(pack2(trB[e], trB[e]), fj, sB);
        }
        *(ull*)&sc[ts * 36 + j0]        = sA;
        *(ull*)&sc[(ts + 16) * 36 + j0] = sB;
    }
    __syncthreads();

    for (int rep = 0; rep < 4; ++rep) {
        const int r = wid * 4 + rep;
        float v = sc[r * 36 + lane];
        float mx = v;
#pragma unroll
        for (int off = 16; off; off >>= 1)
            mx = fmaxf(mx, __shfl_xor_sync(0xffffffffu, mx, off));
        const float pe = __expf(v - mx);
        float ssum = pe;
#pragma unroll
        for (int off = 16; off; off >>= 1)
            ssum += __shfl_xor_sync(0xffffffffu, ssum, off);
        sc[r * 36 + lane] = pe * __fdividef(1.0f, ssum);
    }
    __syncthreads();

    {
        const int d0 = ths * 4;
        ull oA0 = 0, oA1 = 0, oB0 = 0, oB1 = 0;
        const float* pA = sc + ts * 36;
        const float* pB = sc + (ts + 16) * 36;
#pragma unroll 4
        for (int j = 0; j < 32; ++j) {
            const ull p0 = pack2(pA[j], pA[j]);
            const ull p1 = pack2(pB[j], pB[j]);
            const ulonglong2 v = *(const ulonglong2*)&vm[j * 68 + d0];
            oA0 = ffma2(p0, v.x, oA0); oA1 = ffma2(p0, v.y, oA1);
            oB0 = ffma2(p1, v.x, oB0); oB1 = ffma2(p1, v.y, oB1);
        }
        *(ull*)&om[ts * 68 + d0]            = oA0;
        *(ull*)&om[ts * 68 + d0 + 2]        = oA1;
        *(ull*)&om[(ts + 16) * 68 + d0]     = oB0;
        *(ull*)&om[(ts + 16) * 68 + d0 + 2] = oB1;
    }
    __syncthreads();

    {
        ull z[4];
#pragma unroll
        for (int r = 0; r < 4; ++r)
            z[r] = *(const ull*)&ft[(tgp + 8 * r) * 68 + dp];
        const float* wop = wo + dp;
#pragma unroll 4
        for (int e = 0; e < 64; ++e) {
            const ull w2 = *(const ull*)(wop + e * 64);
#pragma unroll
            for (int r = 0; r < 4; ++r) {
                const float a = om[(tgp + 8 * r) * 68 + e];
                z[r] = ffma2(pack2(a, a), w2, z[r]);
            }
        }
        const float2 z0 = unpack2(z[0]), z1 = unpack2(z[1]);
        const float2 z2 = unpack2(z[2]), z3 = unpack2(z[3]);
        red[tgp * 64 + dp]     = fmaxf(fmaxf(z0.x, z1.x), fmaxf(z2.x, z3.x));
        red[tgp * 64 + dp + 1] = fmaxf(fmaxf(z0.y, z1.y), fmaxf(z2.y, z3.y));
    }
    __syncthreads();
    if (tid < 64) {
        float m = red[tid];
#pragma unroll
        for (int w = 1; w < 8; ++w) m = fmaxf(m, red[w * 64 + tid]);
        g_feat2[(size_t)g * 64 + tid] = m;
    }
}

// ---------------- proj2 (unchanged) ----------------
__global__ void __launch_bounds__(256) proj2_kernel(
    const float* __restrict__ wv2, const float* __restrict__ wp2,
    const float* __restrict__ bp2) {
    __shared__ float ft2[32 * 68];
    __shared__ float Ms[4096], Wv[4096], Wp[192], Bp[64];
    __shared__ float px[32], py[32], pz[32];

    const int b  = blockIdx.x >> 6;
    const int t0 = (blockIdx.x & 63) * 32;
    const int tid = threadIdx.x;

    for (int i = tid; i < 4096; i += 256) { Ms[i] = g_M2[i]; Wv[i] = wv2[i]; }
    if (tid < 192) Wp[tid] = wp2[tid];
    if (tid < 64)  Bp[tid] = bp2[tid];
#pragma unroll
    for (int r = 0; r < 2; ++r) {
        const int f4 = tid + r * 256;
        const int tt = f4 >> 4, c4 = (f4 & 15) * 4;
        *(float4*)&ft2[tt * 68 + c4] =
            *(const float4*)&g_feat2[((size_t)(b * NP + t0 + tt)) * 64 + c4];
    }
    if (tid < 32) {
        px[tid] = g_newxyz[((size_t)(b * NP + t0 + tid)) * 3 + 0];
        py[tid] = g_newxyz[((size_t)(b * NP + t0 + tid)) * 3 + 1];
        pz[tid] = g_newxyz[((size_t)(b * NP + t0 + tid)) * 3 + 2];
    }
    __syncthreads();

    const int t  = tid >> 3;
    const int d0 = (tid & 7) * 8;
    float aq[8] = {0,0,0,0,0,0,0,0};
    float av[8] = {0,0,0,0,0,0,0,0};
    const float* fr = ft2 + t * 68;
#pragma unroll 4
    for (int e = 0; e < 64; ++e) {
        const float f = fr[e];
        const float4 m0 = *(const float4*)&Ms[e * 64 + d0];
        const float4 m1 = *(const float4*)&Ms[e * 64 + d0 + 4];
        const float4 v0 = *(const float4*)&Wv[e * 64 + d0];
        const float4 v1 = *(const float4*)&Wv[e * 64 + d0 + 4];
        aq[0] += f * m0.x; aq[1] += f * m0.y; aq[2] += f * m0.z; aq[3] += f * m0.w;
        aq[4] += f * m1.x; aq[5] += f * m1.y; aq[6] += f * m1.z; aq[7] += f * m1.w;
        av[0] += f * v0.x; av[1] += f * v0.y; av[2] += f * v0.z; av[3] += f * v0.w;
        av[4] += f * v1.x; av[5] += f * v1.y; av[6] += f * v1.z; av[7] += f * v1.w;
    }
    const float X = px[t], Y = py[t], Z = pz[t];
#pragma unroll
    for (int i = 0; i < 8; ++i)
        av[i] += X * Wp[d0 + i] + Y * Wp[64 + d0 + i] + Z * Wp[128 + d0 + i] + Bp[d0 + i];

    const size_t o = ((size_t)(b * NP + t0 + t)) * 64 + d0;
    *(float4*)&g_qp[o]     = make_float4(aq[0], aq[1], aq[2], aq[3]);
    *(float4*)&g_qp[o + 4] = make_float4(aq[4], aq[5], aq[6], aq[7]);
    *(float4*)&g_v[o]      = make_float4(av[0], av[1], av[2], av[3]);
    *(float4*)&g_v[o + 4]  = make_float4(av[4], av[5], av[6], av[7]);
}

// ---------------- attn2 flash (R14: double-buffered K/V) ----------------
__global__ void __launch_bounds__(256) flash_kernel() {
    __shared__ float qs[32 * 68];
    __shared__ float ks[2][32 * 68];
    __shared__ float vs[2][32 * 68];
    __shared__ float ps[8 * 144];

    const int b   = blockIdx.y;
    const int q0  = blockIdx.x * 32;
    const int tid = threadIdx.x;
    const int lane = tid & 31, wid = tid >> 5;

#pragma unroll
    for (int r = 0; r < 2; ++r) {
        const int f4 = tid + r * 256;
        const int tt = f4 >> 4, c4 = (f4 & 15) * 4;
        *(float4*)&qs[tt * 68 + c4] =
            *(const float4*)&g_qp[((size_t)(b * NP + q0 + tt)) * 64 + c4];
    }

    float m0q = -1e30f, m1q = -1e30f, m2q = -1e30f, m3q = -1e30f;
    float l0 = 0.f, l1 = 0.f, l2 = 0.f, l3 = 0.f;
    ull acc0 = 0, acc1 = 0, acc2 = 0, acc3 = 0;

    const float* q0r = qs + (wid * 4 + 0) * 68;
    const float* q1r = qs + (wid * 4 + 1) * 68;
    const float* q2r = qs + (wid * 4 + 2) * 68;
    const float* q3r = qs + (wid * 4 + 3) * 68;
    float* pw = ps + wid * 144;

    const int ltt = tid >> 4, lc4 = (tid & 15) * 4;
    const int vtt = tid >> 3, vc8 = (tid & 7) * 4;

#define LOAD_CHUNK(BI, C)                                                        \
    {                                                                            \
        const int kb_ = b * NP + (C) * 32;                                       \
        _Pragma("unroll")                                                        \
        for (int r = 0; r < 2; ++r) {                                            \
            const int tt = ltt + r * 16;                                         \
            *(float4*)&ks[BI][tt * 68 + lc4] =                                   \
                *(const float4*)&g_feat2[((size_t)(kb_ + tt)) * 64 + lc4];       \
        }                                                                        \
        const size_t vrow = ((size_t)(kb_ + vtt)) * 64;                          \
        const float4 a_ = *(const float4*)&g_v[vrow + vc8];                      \
        const float4 b_ = *(const float4*)&g_v[vrow + 32 + vc8];                 \
        *(float4*)&vs[BI][vtt * 68 + 2 * vc8]     = make_float4(a_.x, b_.x, a_.y, b_.y); \
        *(float4*)&vs[BI][vtt * 68 + 2 * vc8 + 4] = make_float4(a_.z, b_.z, a_.w, b_.w); \
    }

    LOAD_CHUNK(0, 0)
    __syncthreads();

    for (int c = 0; c < NP / 32; ++c) {
        const int bi = c & 1;
        if (c + 1 < NP / 32) LOAD_CHUNK(bi ^ 1, c + 1)

        ull sp0 = 0, sp1 = 0, sp2 = 0, sp3 = 0;
        const float* krow = ks[bi] + lane * 68;
#pragma unroll
        for (int e4 = 0; e4 < 16; ++e4) {
            const ulonglong2 k4 = *(const ulonglong2*)&krow[e4 * 4];
            ulonglong2 a;
            a = *(const ulonglong2*)&q0r[e4 * 4];
            sp0 = ffma2(a.x, k4.x, sp0); sp0 = ffma2(a.y, k4.y, sp0);
            a = *(const ulonglong2*)&q1r[e4 * 4];
            sp1 = ffma2(a.x, k4.x, sp1); sp1 = ffma2(a.y, k4.y, sp1);
            a = *(const ulonglong2*)&q2r[e4 * 4];
            sp2 = ffma2(a.x, k4.x, sp2); sp2 = ffma2(a.y, k4.y, sp2);
            a = *(const ulonglong2*)&q3r[e4 * 4];
            sp3 = ffma2(a.x, k4.x, sp3); sp3 = ffma2(a.y, k4.y, sp3);
        }
        const float2 u0 = unpack2(sp0), u1 = unpack2(sp1);
        const float2 u2 = unpack2(sp2), u3 = unpack2(sp3);
        float s0 = u0.x + u0.y, s1 = u1.x + u1.y, s2 = u2.x + u2.y, s3 = u3.x + u3.y;

#define FLASH_SM(S, M, L, ACC, QQ)                                           \
        {                                                                    \
            float cm = S;                                                    \
            cm = fmaxf(cm, __shfl_xor_sync(0xffffffffu, cm, 16));            \
            cm = fmaxf(cm, __shfl_xor_sync(0xffffffffu, cm, 8));             \
            cm = fmaxf(cm, __shfl_xor_sync(0xffffffffu, cm, 4));             \
            cm = fmaxf(cm, __shfl_xor_sync(0xffffffffu, cm, 2));             \
            cm = fmaxf(cm, __shfl_xor_sync(0xffffffffu, cm, 1));             \
            const float mn = fmaxf(M, cm);                                   \
            const float corr = __expf(M - mn);                               \
            const float pe = __expf(S - mn);                                 \
            float sp = pe;                                                   \
            sp += __shfl_xor_sync(0xffffffffu, sp, 16);                      \
            sp += __shfl_xor_sync(0xffffffffu, sp, 8);                       \
            sp += __shfl_xor_sync(0xffffffffu, sp, 4);                       \
            sp += __shfl_xor_sync(0xffffffffu, sp, 2);                       \
            sp += __shfl_xor_sync(0xffffffffu, sp, 1);                       \
            L = L * corr + sp;                                               \
            ACC = fmul2(ACC, pack2(corr, corr));                             \
            pw[QQ * 36 + lane] = pe;                                         \
            M = mn;                                                          \
        }
        FLASH_SM(s0, m0q, l0, acc0, 0)
        FLASH_SM(s1, m1q, l1, acc1, 1)
        FLASH_SM(s2, m2q, l2, acc2, 2)
        FLASH_SM(s3, m3q, l3, acc3, 3)
#undef FLASH_SM
        __syncwarp();

        const float* vb = vs[bi];
#pragma unroll
        for (int j4 = 0; j4 < 8; ++j4) {
            float pa0[4], pa1[4], pa2[4], pa3[4];
            *(float4*)pa0 = *(const float4*)&pw[0   + j4 * 4];
            *(float4*)pa1 = *(const float4*)&pw[36  + j4 * 4];
            *(float4*)pa2 = *(const float4*)&pw[72  + j4 * 4];
            *(float4*)pa3 = *(const float4*)&pw[108 + j4 * 4];
#pragma unroll
            for (int jj = 0; jj < 4; ++jj) {
                const int j = j4 * 4 + jj;
                const ull v2 = *(const ull*)&vb[j * 68 + lane * 2];
                acc0 = ffma2(pack2(pa0[jj], pa0[jj]), v2, acc0);
                acc1 = ffma2(pack2(pa1[jj], pa1[jj]), v2, acc1);
                acc2 = ffma2(pack2(pa2[jj], pa2[jj]), v2, acc2);
                acc3 = ffma2(pack2(pa3[jj], pa3[jj]), v2, acc3);
            }
        }
        __syncthreads();
    }
#undef LOAD_CHUNK

    const size_t ob = ((size_t)(b * NP + q0 + wid * 4)) * 64;
    const float2 o0 = unpack2(acc0), o1 = unpack2(acc1);
    const float2 o2 = unpack2(acc2), o3 = unpack2(acc3);
    g_o[ob + lane]       = o0.x / l0;
    g_o[ob + 32 + lane]  = o0.y / l0;
    g_o[ob + 64 + lane]  = o1.x / l1;
    g_o[ob + 96 + lane]  = o1.y / l1;
    g_o[ob + 128 + lane] = o2.x / l2;
    g_o[ob + 160 + lane] = o2.y / l2;
    g_o[ob + 192 + lane] = o3.x / l3;
    g_o[ob + 224 + lane] = o3.y / l3;
}

// ---------------- final (unchanged) ----------------
__global__ void __launch_bounds__(256) final_kernel(const float* __restrict__ wo,
                                                    float* __restrict__ out2) {
    __shared__ float ot[32 * 68];
    __shared__ float Wo[4096];
    __shared__ float zs[32 * 68];

    const int b  = blockIdx.x >> 6;
    const int t0 = (blockIdx.x & 63) * 32;
    const int tid = threadIdx.x;

    for (int i = tid; i < 4096; i += 256) Wo[i] = wo[i];
#pragma unroll
    for (int r = 0; r < 2; ++r) {
        const int f4 = tid + r * 256;
        const int tt = f4 >> 4, c4 = (f4 & 15) * 4;
        *(float4*)&ot[tt * 68 + c4] =
            *(const float4*)&g_o[((size_t)(b * NP + t0 + tt)) * 64 + c4];
    }
    __syncthreads();

    const int t  = tid >> 3;
    const int d0 = (tid & 7) * 8;
    float z[8];
    {
        const size_t fo = ((size_t)(b * NP + t0 + t)) * 64 + d0;
        const float4 f0 = *(const float4*)&g_feat2[fo];
        const float4 f1 = *(const float4*)&g_feat2[fo + 4];
        z[0] = f0.x; z[1] = f0.y; z[2] = f0.z; z[3] = f0.w;
        z[4] = f1.x; z[5] = f1.y; z[6] = f1.z; z[7] = f1.w;
    }
    const float* orow = ot + t * 68;
#pragma unroll 4
    for (int e = 0; e < 64; ++e) {
        const float a = orow[e];
        const float4 w0 = *(const float4*)&Wo[e * 64 + d0];
        const float4 w1 = *(const float4*)&Wo[e * 64 + d0 + 4];
        z[0] += a * w0.x; z[1] += a * w0.y; z[2] += a * w0.z; z[3] += a * w0.w;
        z[4] += a * w1.x; z[5] += a * w1.y; z[6] += a * w1.z; z[7] += a * w1.w;
    }
    *(float4*)&zs[t * 68 + d0]     = make_float4(z[0], z[1], z[2], z[3]);
    *(float4*)&zs[t * 68 + d0 + 4] = make_float4(z[4], z[5], z[6], z[7]);
    __syncthreads();

    for (int i = tid; i < 2048; i += 256) {
        const int d = i >> 5, tt = i & 31;
        out2[(size_t)b * DD * NP + (size_t)d * NP + t0 + tt] = zs[tt * 68 + d];
    }
}

// ---------------- launch ----------------
extern "C" void kernel_launch(void* const* d_in, const int* in_sizes, int n_in,
                              void* d_out, int out_size) {
    const float* xyz    = (const float*)d_in[0];
    const float* points = (const float*)d_in[1];
    const float* w1q = (const float*)d_in[2];
    const float* w1k = (const float*)d_in[3];
    const float* w1v = (const float*)d_in[4];
    const float* w1o = (const float*)d_in[5];
    const float* w1p = (const float*)d_in[6];
    const float* b1p = (const float*)d_in[7];
    const float* w2q = (const float*)d_in[8];
    const float* w2k = (const float*)d_in[9];
    const float* w2v = (const float*)d_in[10];
    const float* w2o = (const float*)d_in[11];
    const float* w2p = (const float*)d_in[12];
    const float* b2p = (const float*)d_in[13];

    float* out  = (float*)d_out;
    float* out2 = out + (size_t)BB * 3 * NP;

    const int smFps = 3 * NN * 4 + 64 * 8 + 16;
    const int smBq  = 3 * NN * 4;

    cudaFuncSetAttribute(fps_kernel,       cudaFuncAttributeMaxDynamicSharedMemorySize, smFps);
    cudaFuncSetAttribute(ballquery_kernel, cudaFuncAttributeMaxDynamicSharedMemorySize, smBq);
    cudaFuncSetAttribute(attn1_kernel,     cudaFuncAttributeMaxDynamicSharedMemorySize, A1_SMEM_BYTES);

    zerosync_kernel<<<BB * NP * FPSC / 256, 256>>>();
    mprep_kernel<<<2, 256>>>(w1q, w1k, w2q, w2k);
    fps_kernel<<<BB * FPSC, 1024, smFps>>>(xyz, out);
    ballquery_kernel<<<dim3(NP / 8, BB), 256, smBq>>>(xyz);
    attn1_kernel<<<BB * NP, 256, A1_SMEM_BYTES>>>(xyz, points, w1v, w1o, w1p, b1p);
    proj2_kernel<<<BB * 64, 256>>>(w2v, w2p, b2p);
    flash_kernel<<<dim3(NP / 32, BB), 256>>>();
    final_kernel<<<BB * 64, 256>>>(w2o, out2);
}

// round 17
// speedup vs baseline: 2.7118x; 2.7118x over previous
#include <cuda_runtime.h>
#include <math.h>
#include <stdint.h>

#define BB 8
#define NN 8192
#define NP 2048
#define NS 32
#define DINC 61
#define DD 64

typedef unsigned long long ull;
__device__ __forceinline__ ull pack2(float lo, float hi) {
    ull r; asm("mov.b64 %0, {%1,%2};" : "=l"(r) : "f"(lo), "f"(hi)); return r;
}
__device__ __forceinline__ float2 unpack2(ull v) {
    float2 r; asm("mov.b64 {%0,%1}, %2;" : "=f"(r.x), "=f"(r.y) : "l"(v)); return r;
}
__device__ __forceinline__ ull ffma2(ull a, ull b, ull c) {
    ull d; asm("fma.rn.f32x2 %0, %1, %2, %3;" : "=l"(d) : "l"(a), "l"(b), "l"(c)); return d;
}
__device__ __forceinline__ ull fadd2(ull a, ull b) {
    ull d; asm("add.rn.f32x2 %0, %1, %2;" : "=l"(d) : "l"(a), "l"(b)); return d;
}
__device__ __forceinline__ ull fmul2(ull a, ull b) {
    ull d; asm("mul.rn.f32x2 %0, %1, %2;" : "=l"(d) : "l"(a), "l"(b)); return d;
}

__device__ float g_newxyz[BB * NP * 3];
__device__ int   g_gi[BB * NP * NS];
__device__ float g_feat2[BB * NP * DD];
__device__ float g_qp[BB * NP * DD];
__device__ float g_v[BB * NP * DD];
__device__ float g_o[BB * NP * DD];
__device__ float g_M1[DD * DD];
__device__ float g_M2[DD * DD];

// ---------------- M = 0.125 * Wq @ Wk^T ----------------
__global__ void __launch_bounds__(256) mprep_kernel(
    const float* __restrict__ q1, const float* __restrict__ k1,
    const float* __restrict__ q2, const float* __restrict__ k2) {
    __shared__ float sq[4096], sk[4096];
    const float* q = blockIdx.x ? q2 : q1;
    const float* k = blockIdx.x ? k2 : k1;
    float* M = blockIdx.x ? g_M2 : g_M1;
    const int tid = threadIdx.x;
    for (int i = tid; i < 4096; i += 256) { sq[i] = q[i]; sk[i] = k[i]; }
    __syncthreads();
    for (int o = 0; o < 16; ++o) {
        const int idx = tid + o * 256;
        const int a = idx >> 6, c = idx & 63;
        float s = 0.f;
#pragma unroll 8
        for (int d = 0; d < 64; ++d) s += sq[a * 64 + d] * sk[c * 64 + d];
        M[idx] = 0.125f * s;
    }
}

// ---------------- FPS: one barrier/iter, REDUX-only reduction (no atomics) ----------------
__global__ void __launch_bounds__(1024) fps_kernel(const float* __restrict__ xyz,
                                                   float* __restrict__ out1) {
    extern __shared__ float sm[];
    float* sx  = sm;
    float* sy  = sm + NN;
    float* sz  = sm + 2 * NN;
    ull*  wkey = (ull*)(sm + 3 * NN);   // 2 x 32 slots

    const int b   = blockIdx.x;
    const int tid = threadIdx.x;
    const int lane = tid & 31, wid = tid >> 5;
    const float* xb = xyz + (size_t)b * 3 * NN;

    ull x2[4], y2[4], z2[4];
    float pd[8];
#pragma unroll
    for (int p = 0; p < 4; ++p) {
        const int i0 = tid + (2 * p) * 1024, i1 = i0 + 1024;
        const float xa = xb[i0], xbv = xb[i1];
        const float ya = xb[NN + i0], ybv = xb[NN + i1];
        const float za = xb[2 * NN + i0], zbv = xb[2 * NN + i1];
        x2[p] = pack2(xa, xbv); y2[p] = pack2(ya, ybv); z2[p] = pack2(za, zbv);
        sx[i0] = xa; sx[i1] = xbv; sy[i0] = ya; sy[i1] = ybv; sz[i0] = za; sz[i1] = zbv;
        pd[2 * p] = 1e10f; pd[2 * p + 1] = 1e10f;
    }
    __syncthreads();

    int cur = 0;
    for (int it = 0; it < NP; ++it) {
        const float c0 = sx[cur], c1 = sy[cur], c2 = sz[cur];
        if (tid == 0) {
            g_newxyz[((size_t)b * NP + it) * 3 + 0] = c0;
            g_newxyz[((size_t)b * NP + it) * 3 + 1] = c1;
            g_newxyz[((size_t)b * NP + it) * 3 + 2] = c2;
            out1[(size_t)b * 3 * NP + it]          = c0;
            out1[(size_t)b * 3 * NP + NP + it]     = c1;
            out1[(size_t)b * 3 * NP + 2 * NP + it] = c2;
        }
        // distance math: BIT-IDENTICAL to XLA elementwise lowering (no FMA;
        // x + (-c) == x - c in IEEE; f32x2 ops are componentwise RN)
        const ull n0 = pack2(-c0, -c0), n1 = pack2(-c1, -c1), n2 = pack2(-c2, -c2);
        float tmax = -1.0f;
        int   kbest = 0;
#pragma unroll
        for (int pp = 0; pp < 4; ++pp) {
            const ull dx = fadd2(x2[pp], n0);
            const ull dy = fadd2(y2[pp], n1);
            const ull dz = fadd2(z2[pp], n2);
            const ull d  = fadd2(fadd2(fmul2(dx, dx), fmul2(dy, dy)), fmul2(dz, dz));
            const float2 dv = unpack2(d);
            const float p0 = fminf(pd[2 * pp], dv.x);
            const float p1 = fminf(pd[2 * pp + 1], dv.y);
            pd[2 * pp] = p0; pd[2 * pp + 1] = p1;
            if (p0 > tmax) { tmax = p0; kbest = 2 * pp; }
            if (p1 > tmax) { tmax = p1; kbest = 2 * pp + 1; }
        }
        // stage 1: warp reduce (positive floats: uint bit order == float order)
        const unsigned tb = __float_as_uint(tmax);
        const unsigned wm = __reduce_max_sync(0xffffffffu, tb);
        const unsigned inv = __reduce_max_sync(
            0xffffffffu, (tb == wm) ? ~(unsigned)(tid + kbest * 1024) : 0u);
        ull* buf = wkey + (it & 1) * 32;
        if (lane == 0) buf[wid] = ((ull)wm << 32) | (ull)inv;
        __syncthreads();
        // stage 2: every warp reduces all 32 warp keys (redundant, barrier-free)
        const ull k = buf[lane];
        const unsigned hi = (unsigned)(k >> 32), lo = (unsigned)k;
        const unsigned m2 = __reduce_max_sync(0xffffffffu, hi);
        const unsigned inv2 = __reduce_max_sync(0xffffffffu, (hi == m2) ? lo : 0u);
        cur = (int)(~inv2);
    }
}

// ---------------- ball query (decision-exact) ----------------
__global__ void __launch_bounds__(256) ballquery_kernel(const float* __restrict__ xyz) {
    extern __shared__ float sm[];
    float* sx = sm;
    float* sy = sm + NN;
    float* sz = sm + 2 * NN;

    const int b   = blockIdx.y;
    const int tid = threadIdx.x;
    const float* xb = xyz + (size_t)b * 3 * NN;
    for (int i = tid; i < NN; i += 256) {
        sx[i] = xb[i]; sy[i] = xb[NN + i]; sz[i] = xb[2 * NN + i];
    }
    __syncthreads();

    const int wid = tid >> 5, lane = tid & 31;
    const int s = blockIdx.x * 8 + wid;
    const float r2 = (float)(0.2 * 0.2);

    const float c0 = g_newxyz[((size_t)b * NP + s) * 3 + 0];
    const float c1 = g_newxyz[((size_t)b * NP + s) * 3 + 1];
    const float c2 = g_newxyz[((size_t)b * NP + s) * 3 + 2];
    const float sqc = __fadd_rn(__fadd_rn(__fmul_rn(c0, c0), __fmul_rn(c1, c1)),
                                __fmul_rn(c2, c2));
    const size_t gbase = ((size_t)b * NP + s) * NS;

    int count = 0;
    int firstIdx = -1;
    for (int base = 0; base < NN && count < NS; base += 32) {
        const int i = base + lane;
        const float x = sx[i], y = sy[i], z = sz[i];
        const float sqx = __fadd_rn(__fadd_rn(__fmul_rn(x, x), __fmul_rn(y, y)),
                                    __fmul_rn(z, z));
        const float cx = fmaf(c2, z, fmaf(c1, y, __fmul_rn(c0, x)));
        const float sqr = __fsub_rn(__fadd_rn(sqc, sqx), __fmul_rn(2.0f, cx));
        const bool hit = !(sqr > r2);
        const unsigned mask = __ballot_sync(0xffffffffu, hit);
        if (firstIdx < 0 && mask) firstIdx = base + __ffs(mask) - 1;
        if (hit) {
            int slot = count + __popc(mask & ((1u << lane) - 1u));
            if (slot < NS) g_gi[gbase + slot] = i;
        }
        count += __popc(mask);
    }
    int cnt = count < NS ? count : NS;
    for (int j = cnt + lane; j < NS; j += 32) g_gi[gbase + j] = firstIdx;
}

// ---------------- attn1 (R=4 weight amortization; 64-reg safe) ----------------
#define A1_SMEM_BYTES 43008

__global__ void __launch_bounds__(256, 4) attn1_kernel(
    const float* __restrict__ xyz, const float* __restrict__ points,
    const float* __restrict__ wv, const float* __restrict__ wo,
    const float* __restrict__ wp, const float* __restrict__ bp) {
    extern __shared__ float sm[];
    float* ft  = sm;
    float* ftT = sm + 2176;
    float* tm  = sm + 4480;
    float* vm  = sm + 6656;
    float* sc  = sm + 8832;
    float* px  = sm + 9984;
    float* py  = sm + 10016;
    float* pz  = sm + 10048;
    float* red = sm + 10080;
    int* sidx  = (int*)(sm + 10592);
    float* om  = ftT;

    const int g   = blockIdx.x;
    const int b   = g >> 11;
    const int tid = threadIdx.x;
    const int lane = tid & 31, wid = tid >> 5;

    if (tid < 32) {
        const int id = g_gi[(size_t)g * NS + tid];
        sidx[tid] = id;
        const float c0 = g_newxyz[(size_t)g * 3 + 0];
        const float c1 = g_newxyz[(size_t)g * 3 + 1];
        const float c2 = g_newxyz[(size_t)g * 3 + 2];
        const float X = xyz[(size_t)b * 3 * NN + id];
        const float Y = xyz[(size_t)b * 3 * NN + NN + id];
        const float Z = xyz[(size_t)b * 3 * NN + 2 * NN + id];
        px[tid] = X; py[tid] = Y; pz[tid] = Z;
        ft[tid * 68 + 0] = X - c0;
        ft[tid * 68 + 1] = Y - c1;
        ft[tid * 68 + 2] = Z - c2;
    }
    __syncthreads();
    for (int i = tid; i < NS * DINC; i += 256) {
        const int c = i >> 5, j = i & 31;
        ft[j * 68 + 3 + c] = points[(size_t)b * DINC * NN + (size_t)c * NN + sidx[j]];
    }
    __syncthreads();

    const int thp = tid & 31;
    const int dp  = thp * 2;
    const int tgp = tid >> 5;
    {
        ull aM[4] = {0, 0, 0, 0}, aV[4] = {0, 0, 0, 0};
        const float* mp = g_M1 + dp;
        const float* vp = wv + dp;
#pragma unroll 4
        for (int e = 0; e < 64; ++e) {
            const ull m2 = *(const ull*)(mp + e * 64);
            const ull v2 = *(const ull*)(vp + e * 64);
#pragma unroll
            for (int r = 0; r < 4; ++r) {
                const float f = ft[(tgp + 8 * r) * 68 + e];
                const ull f2 = pack2(f, f);
                aM[r] = ffma2(f2, m2, aM[r]);
                aV[r] = ffma2(f2, v2, aV[r]);
            }
        }
        const ull wx = *(const ull*)(wp + dp);
        const ull wy = *(const ull*)(wp + 64 + dp);
        const ull wz = *(const ull*)(wp + 128 + dp);
        const ull wb = *(const ull*)(bp + dp);
#pragma unroll
        for (int r = 0; r < 4; ++r) {
            const int row = tgp + 8 * r;
            aV[r] = ffma2(pack2(px[row], px[row]), wx, aV[r]);
            aV[r] = ffma2(pack2(py[row], py[row]), wy, aV[r]);
            aV[r] = ffma2(pack2(pz[row], pz[row]), wz, aV[r]);
            aV[r] = fadd2(aV[r], wb);
            *(ull*)&tm[row * 68 + dp] = aM[r];
            *(ull*)&vm[row * 68 + dp] = aV[r];
        }
    }
#pragma unroll
    for (int r = 0; r < 8; ++r) {
        const int idx = tid + r * 256;
        const int e = idx >> 5, j = idx & 31;
        ftT[e * 36 + j] = ft[j * 68 + e];
    }
    __syncthreads();

    const int ths = tid & 15;
    const int ts  = tid >> 4;
    {
        const int j0 = ths * 2;
        ull sA = 0, sB = 0;
        const float* trA = tm + ts * 68;
        const float* trB = tm + (ts + 16) * 68;
#pragma unroll 8
        for (int e = 0; e < 64; ++e) {
            const ull fj = *(const ull*)&ftT[e * 36 + j0];
            sA = ffma2(pack2(trA[e], trA[e]), fj, sA);
            sB = ffma2(pack2(trB[e], trB[e]), fj, sB);
        }
        *(ull*)&sc[ts * 36 + j0]        = sA;
        *(ull*)&sc[(ts + 16) * 36 + j0] = sB;
    }
    __syncthreads();

    for (int rep = 0; rep < 4; ++rep) {
        const int r = wid * 4 + rep;
        float v = sc[r * 36 + lane];
        float mx = v;
#pragma unroll
        for (int off = 16; off; off >>= 1)
            mx = fmaxf(mx, __shfl_xor_sync(0xffffffffu, mx, off));
        const float pe = __expf(v - mx);
        float ssum = pe;
#pragma unroll
        for (int off = 16; off; off >>= 1)
            ssum += __shfl_xor_sync(0xffffffffu, ssum, off);
        sc[r * 36 + lane] = pe * __fdividef(1.0f, ssum);
    }
    __syncthreads();

    {
        const int d0 = ths * 4;
        ull oA0 = 0, oA1 = 0, oB0 = 0, oB1 = 0;
        const float* pA = sc + ts * 36;
        const float* pB = sc + (ts + 16) * 36;
#pragma unroll 4
        for (int j = 0; j < 32; ++j) {
            const ull p0 = pack2(pA[j], pA[j]);
            const ull p1 = pack2(pB[j], pB[j]);
            const ulonglong2 v = *(const ulonglong2*)&vm[j * 68 + d0];
            oA0 = ffma2(p0, v.x, oA0); oA1 = ffma2(p0, v.y, oA1);
            oB0 = ffma2(p1, v.x, oB0); oB1 = ffma2(p1, v.y, oB1);
        }
        *(ull*)&om[ts * 68 + d0]            = oA0;
        *(ull*)&om[ts * 68 + d0 + 2]        = oA1;
        *(ull*)&om[(ts + 16) * 68 + d0]     = oB0;
        *(ull*)&om[(ts + 16) * 68 + d0 + 2] = oB1;
    }
    __syncthreads();

    {
        ull z[4];
#pragma unroll
        for (int r = 0; r < 4; ++r)
            z[r] = *(const ull*)&ft[(tgp + 8 * r) * 68 + dp];
        const float* wop = wo + dp;
#pragma unroll 4
        for (int e = 0; e < 64; ++e) {
            const ull w2 = *(const ull*)(wop + e * 64);
#pragma unroll
            for (int r = 0; r < 4; ++r) {
                const float a = om[(tgp + 8 * r) * 68 + e];
                z[r] = ffma2(pack2(a, a), w2, z[r]);
            }
        }
        const float2 z0 = unpack2(z[0]), z1 = unpack2(z[1]);
        const float2 z2 = unpack2(z[2]), z3 = unpack2(z[3]);
        red[tgp * 64 + dp]     = fmaxf(fmaxf(z0.x, z1.x), fmaxf(z2.x, z3.x));
        red[tgp * 64 + dp + 1] = fmaxf(fmaxf(z0.y, z1.y), fmaxf(z2.y, z3.y));
    }
    __syncthreads();
    if (tid < 64) {
        float m = red[tid];
#pragma unroll
        for (int w = 1; w < 8; ++w) m = fmaxf(m, red[w * 64 + tid]);
        g_feat2[(size_t)g * 64 + tid] = m;
    }
}

// ---------------- proj2 ----------------
__global__ void __launch_bounds__(256) proj2_kernel(
    const float* __restrict__ wv2, const float* __restrict__ wp2,
    const float* __restrict__ bp2) {
    __shared__ float ft2[32 * 68];
    __shared__ float Ms[4096], Wv[4096], Wp[192], Bp[64];
    __shared__ float px[32], py[32], pz[32];

    const int b  = blockIdx.x >> 6;
    const int t0 = (blockIdx.x & 63) * 32;
    const int tid = threadIdx.x;

    for (int i = tid; i < 4096; i += 256) { Ms[i] = g_M2[i]; Wv[i] = wv2[i]; }
    if (tid < 192) Wp[tid] = wp2[tid];
    if (tid < 64)  Bp[tid] = bp2[tid];
#pragma unroll
    for (int r = 0; r < 2; ++r) {
        const int f4 = tid + r * 256;
        const int tt = f4 >> 4, c4 = (f4 & 15) * 4;
        *(float4*)&ft2[tt * 68 + c4] =
            *(const float4*)&g_feat2[((size_t)(b * NP + t0 + tt)) * 64 + c4];
    }
    if (tid < 32) {
        px[tid] = g_newxyz[((size_t)(b * NP + t0 + tid)) * 3 + 0];
        py[tid] = g_newxyz[((size_t)(b * NP + t0 + tid)) * 3 + 1];
        pz[tid] = g_newxyz[((size_t)(b * NP + t0 + tid)) * 3 + 2];
    }
    __syncthreads();

    const int t  = tid >> 3;
    const int d0 = (tid & 7) * 8;
    float aq[8] = {0,0,0,0,0,0,0,0};
    float av[8] = {0,0,0,0,0,0,0,0};
    const float* fr = ft2 + t * 68;
#pragma unroll 4
    for (int e = 0; e < 64; ++e) {
        const float f = fr[e];
        const float4 m0 = *(const float4*)&Ms[e * 64 + d0];
        const float4 m1 = *(const float4*)&Ms[e * 64 + d0 + 4];
        const float4 v0 = *(const float4*)&Wv[e * 64 + d0];
        const float4 v1 = *(const float4*)&Wv[e * 64 + d0 + 4];
        aq[0] += f * m0.x; aq[1] += f * m0.y; aq[2] += f * m0.z; aq[3] += f * m0.w;
        aq[4] += f * m1.x; aq[5] += f * m1.y; aq[6] += f * m1.z; aq[7] += f * m1.w;
        av[0] += f * v0.x; av[1] += f * v0.y; av[2] += f * v0.z; av[3] += f * v0.w;
        av[4] += f * v1.x; av[5] += f * v1.y; av[6] += f * v1.z; av[7] += f * v1.w;
    }
    const float X = px[t], Y = py[t], Z = pz[t];
#pragma unroll
    for (int i = 0; i < 8; ++i)
        av[i] += X * Wp[d0 + i] + Y * Wp[64 + d0 + i] + Z * Wp[128 + d0 + i] + Bp[d0 + i];

    const size_t o = ((size_t)(b * NP + t0 + t)) * 64 + d0;
    *(float4*)&g_qp[o]     = make_float4(aq[0], aq[1], aq[2], aq[3]);
    *(float4*)&g_qp[o + 4] = make_float4(aq[4], aq[5], aq[6], aq[7]);
    *(float4*)&g_v[o]      = make_float4(av[0], av[1], av[2], av[3]);
    *(float4*)&g_v[o + 4]  = make_float4(av[4], av[5], av[6], av[7]);
}

// ---------------- attn2 flash: interleaved V + packed AV accumulators ----------------
__global__ void __launch_bounds__(256) flash_kernel() {
    __shared__ float qs[32 * 68];
    __shared__ float ks[32 * 68];
    __shared__ float vs[32 * 68];
    __shared__ float ps[8 * 144];

    const int b   = blockIdx.y;
    const int q0  = blockIdx.x * 32;
    const int tid = threadIdx.x;
    const int lane = tid & 31, wid = tid >> 5;

#pragma unroll
    for (int r = 0; r < 2; ++r) {
        const int f4 = tid + r * 256;
        const int tt = f4 >> 4, c4 = (f4 & 15) * 4;
        *(float4*)&qs[tt * 68 + c4] =
            *(const float4*)&g_qp[((size_t)(b * NP + q0 + tt)) * 64 + c4];
    }

    float m0q = -1e30f, m1q = -1e30f, m2q = -1e30f, m3q = -1e30f;
    float l0 = 0.f, l1 = 0.f, l2 = 0.f, l3 = 0.f;
    ull acc0 = 0, acc1 = 0, acc2 = 0, acc3 = 0;

    const float* q0r = qs + (wid * 4 + 0) * 68;
    const float* q1r = qs + (wid * 4 + 1) * 68;
    const float* q2r = qs + (wid * 4 + 2) * 68;
    const float* q3r = qs + (wid * 4 + 3) * 68;
    float* pw = ps + wid * 144;

    const int vtt = tid >> 3, vc8 = (tid & 7) * 4;

    for (int c = 0; c < NP / 32; ++c) {
        __syncthreads();
        const int kb = b * NP + c * 32;
#pragma unroll
        for (int r = 0; r < 2; ++r) {
            const int f4 = tid + r * 256;
            const int tt = f4 >> 4, c4 = (f4 & 15) * 4;
            *(float4*)&ks[tt * 68 + c4] =
                *(const float4*)&g_feat2[((size_t)(kb + tt)) * 64 + c4];
        }
        {
            const size_t vrow = ((size_t)(kb + vtt)) * 64;
            const float4 a = *(const float4*)&g_v[vrow + vc8];
            const float4 bb = *(const float4*)&g_v[vrow + 32 + vc8];
            *(float4*)&vs[vtt * 68 + 2 * vc8]     = make_float4(a.x, bb.x, a.y, bb.y);
            *(float4*)&vs[vtt * 68 + 2 * vc8 + 4] = make_float4(a.z, bb.z, a.w, bb.w);
        }
        __syncthreads();

        ull sp0 = 0, sp1 = 0, sp2 = 0, sp3 = 0;
        const float* krow = ks + lane * 68;
#pragma unroll
        for (int e4 = 0; e4 < 16; ++e4) {
            const ulonglong2 k4 = *(const ulonglong2*)&krow[e4 * 4];
            ulonglong2 a;
            a = *(const ulonglong2*)&q0r[e4 * 4];
            sp0 = ffma2(a.x, k4.x, sp0); sp0 = ffma2(a.y, k4.y, sp0);
            a = *(const ulonglong2*)&q1r[e4 * 4];
            sp1 = ffma2(a.x, k4.x, sp1); sp1 = ffma2(a.y, k4.y, sp1);
            a = *(const ulonglong2*)&q2r[e4 * 4];
            sp2 = ffma2(a.x, k4.x, sp2); sp2 = ffma2(a.y, k4.y, sp2);
            a = *(const ulonglong2*)&q3r[e4 * 4];
            sp3 = ffma2(a.x, k4.x, sp3); sp3 = ffma2(a.y, k4.y, sp3);
        }
        const float2 u0 = unpack2(sp0), u1 = unpack2(sp1);
        const float2 u2 = unpack2(sp2), u3 = unpack2(sp3);
        float s0 = u0.x + u0.y, s1 = u1.x + u1.y, s2 = u2.x + u2.y, s3 = u3.x + u3.y;

#define FLASH_SM(S, M, L, ACC, QQ)                                           \
        {                                                                    \
            float cm = S;                                                    \
            cm = fmaxf(cm, __shfl_xor_sync(0xffffffffu, cm, 16));            \
            cm = fmaxf(cm, __shfl_xor_sync(0xffffffffu, cm, 8));             \
            cm = fmaxf(cm, __shfl_xor_sync(0xffffffffu, cm, 4));             \
            cm = fmaxf(cm, __shfl_xor_sync(0xffffffffu, cm, 2));             \
            cm = fmaxf(cm, __shfl_xor_sync(0xffffffffu, cm, 1));             \
            const float mn = fmaxf(M, cm);                                   \
            const float corr = __expf(M - mn);                               \
            const float pe = __expf(S - mn);                                 \
            float sp = pe;                                                   \
            sp += __shfl_xor_sync(0xffffffffu, sp, 16);                      \
            sp += __shfl_xor_sync(0xffffffffu, sp, 8);                       \
            sp += __shfl_xor_sync(0xffffffffu, sp, 4);                       \
            sp += __shfl_xor_sync(0xffffffffu, sp, 2);                       \
            sp += __shfl_xor_sync(0xffffffffu, sp, 1);                       \
            L = L * corr + sp;                                               \
            ACC = fmul2(ACC, pack2(corr, corr));                             \
            pw[QQ * 36 + lane] = pe;                                         \
            M = mn;                                                          \
        }
        FLASH_SM(s0, m0q, l0, acc0, 0)
        FLASH_SM(s1, m1q, l1, acc1, 1)
        FLASH_SM(s2, m2q, l2, acc2, 2)
        FLASH_SM(s3, m3q, l3, acc3, 3)
#undef FLASH_SM
        __syncwarp();

#pragma unroll
        for (int j4 = 0; j4 < 8; ++j4) {
            float pa0[4], pa1[4], pa2[4], pa3[4];
            *(float4*)pa0 = *(const float4*)&pw[0   + j4 * 4];
            *(float4*)pa1 = *(const float4*)&pw[36  + j4 * 4];
            *(float4*)pa2 = *(const float4*)&pw[72  + j4 * 4];
            *(float4*)pa3 = *(const float4*)&pw[108 + j4 * 4];
#pragma unroll
            for (int jj = 0; jj < 4; ++jj) {
                const int j = j4 * 4 + jj;
                const ull v2 = *(const ull*)&vs[j * 68 + lane * 2];
                acc0 = ffma2(pack2(pa0[jj], pa0[jj]), v2, acc0);
                acc1 = ffma2(pack2(pa1[jj], pa1[jj]), v2, acc1);
                acc2 = ffma2(pack2(pa2[jj], pa2[jj]), v2, acc2);
                acc3 = ffma2(pack2(pa3[jj], pa3[jj]), v2, acc3);
            }
        }
        __syncwarp();
    }

    const size_t ob = ((size_t)(b * NP + q0 + wid * 4)) * 64;
    const float2 o0 = unpack2(acc0), o1 = unpack2(acc1);
    const float2 o2 = unpack2(acc2), o3 = unpack2(acc3);
    g_o[ob + lane]       = o0.x / l0;
    g_o[ob + 32 + lane]  = o0.y / l0;
    g_o[ob + 64 + lane]  = o1.x / l1;
    g_o[ob + 96 + lane]  = o1.y / l1;
    g_o[ob + 128 + lane] = o2.x / l2;
    g_o[ob + 160 + lane] = o2.y / l2;
    g_o[ob + 192 + lane] = o3.x / l3;
    g_o[ob + 224 + lane] = o3.y / l3;
}

// ---------------- final ----------------
__global__ void __launch_bounds__(256) final_kernel(const float* __restrict__ wo,
                                                    float* __restrict__ out2) {
    __shared__ float ot[32 * 68];
    __shared__ float Wo[4096];
    __shared__ float zs[32 * 68];

    const int b  = blockIdx.x >> 6;
    const int t0 = (blockIdx.x & 63) * 32;
    const int tid = threadIdx.x;

    for (int i = tid; i < 4096; i += 256) Wo[i] = wo[i];
#pragma unroll
    for (int r = 0; r < 2; ++r) {
        const int f4 = tid + r * 256;
        const int tt = f4 >> 4, c4 = (f4 & 15) * 4;
        *(float4*)&ot[tt * 68 + c4] =
            *(const float4*)&g_o[((size_t)(b * NP + t0 + tt)) * 64 + c4];
    }
    __syncthreads();

    const int t  = tid >> 3;
    const int d0 = (tid & 7) * 8;
    float z[8];
    {
        const size_t fo = ((size_t)(b * NP + t0 + t)) * 64 + d0;
        const float4 f0 = *(const float4*)&g_feat2[fo];
        const float4 f1 = *(const float4*)&g_feat2[fo + 4];
        z[0] = f0.x; z[1] = f0.y; z[2] = f0.z; z[3] = f0.w;
        z[4] = f1.x; z[5] = f1.y; z[6] = f1.z; z[7] = f1.w;
    }
    const float* orow = ot + t * 68;
#pragma unroll 4
    for (int e = 0; e < 64; ++e) {
        const float a = orow[e];
        const float4 w0 = *(const float4*)&Wo[e * 64 + d0];
        const float4 w1 = *(const float4*)&Wo[e * 64 + d0 + 4];
        z[0] += a * w0.x; z[1] += a * w0.y; z[2] += a * w0.z; z[3] += a * w0.w;
        z[4] += a * w1.x; z[5] += a * w1.y; z[6] += a * w1.z; z[7] += a * w1.w;
    }
    *(float4*)&zs[t * 68 + d0]     = make_float4(z[0], z[1], z[2], z[3]);
    *(float4*)&zs[t * 68 + d0 + 4] = make_float4(z[4], z[5], z[6], z[7]);
    __syncthreads();

    for (int i = tid; i < 2048; i += 256) {
        const int d = i >> 5, tt = i & 31;
        out2[(size_t)b * DD * NP + (size_t)d * NP + t0 + tt] = zs[tt * 68 + d];
    }
}

// ---------------- launch ----------------
extern "C" void kernel_launch(void* const* d_in, const int* in_sizes, int n_in,
                              void* d_out, int out_size) {
    const float* xyz    = (const float*)d_in[0];
    const float* points = (const float*)d_in[1];
    const float* w1q = (const float*)d_in[2];
    const float* w1k = (const float*)d_in[3];
    const float* w1v = (const float*)d_in[4];
    const float* w1o = (const float*)d_in[5];
    const float* w1p = (const float*)d_in[6];
    const float* b1p = (const float*)d_in[7];
    const float* w2q = (const float*)d_in[8];
    const float* w2k = (const float*)d_in[9];
    const float* w2v = (const float*)d_in[10];
    const float* w2o = (const float*)d_in[11];
    const float* w2p = (const float*)d_in[12];
    const float* b2p = (const float*)d_in[13];

    float* out  = (float*)d_out;
    float* out2 = out + (size_t)BB * 3 * NP;

    const int smFps = 3 * NN * 4 + 64 * 8;
    const int smBq  = 3 * NN * 4;

    cudaFuncSetAttribute(fps_kernel,       cudaFuncAttributeMaxDynamicSharedMemorySize, smFps);
    cudaFuncSetAttribute(ballquery_kernel, cudaFuncAttributeMaxDynamicSharedMemorySize, smBq);
    cudaFuncSetAttribute(attn1_kernel,     cudaFuncAttributeMaxDynamicSharedMemorySize, A1_SMEM_BYTES);

    mprep_kernel<<<2, 256>>>(w1q, w1k, w2q, w2k);
    fps_kernel<<<BB, 1024, smFps>>>(xyz, out);
    ballquery_kernel<<<dim3(NP / 8, BB), 256, smBq>>>(xyz);
    attn1_kernel<<<BB * NP, 256, A1_SMEM_BYTES>>>(xyz, points, w1v, w1o, w1p, b1p);
    proj2_kernel<<<BB * 64, 256>>>(w2v, w2p, b2p);
    flash_kernel<<<dim3(NP / 32, BB), 256>>>();
    final_kernel<<<BB * 64, 256>>>(w2o, out2);
}